// round 11
// baseline (speedup 1.0000x reference)
#include <cuda_runtime.h>
#include <cuda_fp16.h>
#include <cstdint>

#define B_   64
#define N_   5000
#define NP1  5001
#define D_   128
#define TILES 40
#define SPU  20     // smem B row stride in uint2 (==4 mod 16 -> conflict-free LDS.64)

// ------------------------- device scratch (no allocs) -----------------------
__device__ uint2  g_Wb[8 * 128 * 16];                 // fused weights fp16, 8 K=64 sub-slices
__device__ __half g_added[(size_t)B_ * N_ * D_];      // fp16 'added' scratch (82MB)
__device__ float  g_partS[B_ * TILES * D_];
__device__ float  g_partQ[B_ * TILES * D_];
__device__ float  g_mean[B_ * D_];
__device__ float  g_rstd[B_ * D_];

// ------------------------------- helpers ------------------------------------
__device__ __forceinline__ uint32_t cvt2h(float x, float y) {
    __half2 h = __floats2half2_rn(x, y);
    return *reinterpret_cast<uint32_t*>(&h);
}

__device__ __forceinline__ void mma16816(float (&c)[4],
                                         uint32_t a0, uint32_t a1, uint32_t a2, uint32_t a3,
                                         uint32_t b0, uint32_t b1) {
    asm("mma.sync.aligned.m16n8k16.row.col.f32.f16.f16.f32 "
        "{%0,%1,%2,%3}, {%4,%5,%6,%7}, {%8,%9}, {%0,%1,%2,%3};"
        : "+f"(c[0]), "+f"(c[1]), "+f"(c[2]), "+f"(c[3])
        : "r"(a0), "r"(a1), "r"(a2), "r"(a3), "r"(b0), "r"(b1));
}

__device__ __forceinline__ void cp16(void* dst_smem, const void* src) {
    unsigned sa = (unsigned)__cvta_generic_to_shared(dst_smem);
    asm volatile("cp.async.cg.shared.global [%0], [%1], 16;\n" :: "r"(sa), "l"(src));
}
__device__ __forceinline__ void cp_commit() { asm volatile("cp.async.commit_group;\n"); }
template <int N>
__device__ __forceinline__ void cp_wait() { asm volatile("cp.async.wait_group %0;\n" :: "n"(N)); }

// -------------------------- fused weight prep --------------------------------
__global__ void prep_kernel(const float* __restrict__ w_comb,
                            const float* __restrict__ w_left,
                            const float* __restrict__ w_right,
                            const float* __restrict__ w_ff) {
    __shared__ float row[512];
    int n = blockIdx.x, k = threadIdx.x;          // 128 x 128
    row[k] = w_comb[n * 256 + k];
    float a1 = 0.f, a2 = 0.f;
    for (int m = 0; m < 128; ++m) {
        float wc = w_comb[n * 256 + 128 + m];
        a1 = fmaf(wc, w_left[m * 128 + k], a1);
        a2 = fmaf(wc, w_right[m * 128 + k], a2);
    }
    row[128 + k] = a1;
    row[256 + k] = a2;
    row[384 + k] = w_ff[n * 128 + k];
    __syncthreads();
    const int ss = k >> 4, e = k & 15;
    const int c = e >> 2, cq = e & 3;
    const int base = ss * 64;
    const int i0 = base + (c * 8 + cq) * 2;
    const int i1 = base + (c * 8 + cq + 4) * 2;
    uint2 w;
    w.x = cvt2h(row[i0], row[i0 + 1]);
    w.y = cvt2h(row[i1], row[i1 + 1]);
    g_Wb[(ss * 128 + n) * 16 + e] = w;
}

// --------------------------- main fused kernel -------------------------------
#define WBUF_UINT2 (128 * SPU)                            // 2560 uint2 = 20480 B
#define SMEM_W     (8 * WBUF_UINT2 * 8)                   // 163840
#define SMEM_BYTES (SMEM_W + 1024 + 16384)                // 181248

// one K=64 sub-slice over TWO tiles: one B-fragment LDS feeds 2 MMAs
__device__ __forceinline__ void compute_slice_dual(const uint2* __restrict__ sW,
                                                   const float* __restrict__ pA0,
                                                   const float* __restrict__ pA1,
                                                   const float* __restrict__ pB0,
                                                   const float* __restrict__ pB1,
                                                   int cq, int g,
                                                   float (&accA)[16][4],
                                                   float (&accB)[16][4]) {
#pragma unroll
    for (int c = 0; c < 4; ++c) {
        const int kc = c * 16 + cq * 2;
        float2 xA0a = *reinterpret_cast<const float2*>(pA0 + kc);
        float2 xA0b = *reinterpret_cast<const float2*>(pA0 + kc + 8);
        float2 xA1a = *reinterpret_cast<const float2*>(pA1 + kc);
        float2 xA1b = *reinterpret_cast<const float2*>(pA1 + kc + 8);
        float2 xB0a = *reinterpret_cast<const float2*>(pB0 + kc);
        float2 xB0b = *reinterpret_cast<const float2*>(pB0 + kc + 8);
        float2 xB1a = *reinterpret_cast<const float2*>(pB1 + kc);
        float2 xB1b = *reinterpret_cast<const float2*>(pB1 + kc + 8);
        const uint32_t aA0 = cvt2h(xA0a.x, xA0a.y);
        const uint32_t aA1 = cvt2h(xA1a.x, xA1a.y);
        const uint32_t aA2 = cvt2h(xA0b.x, xA0b.y);
        const uint32_t aA3 = cvt2h(xA1b.x, xA1b.y);
        const uint32_t aB0 = cvt2h(xB0a.x, xB0a.y);
        const uint32_t aB1 = cvt2h(xB1a.x, xB1a.y);
        const uint32_t aB2 = cvt2h(xB0b.x, xB0b.y);
        const uint32_t aB3 = cvt2h(xB1b.x, xB1b.y);
        const int e = c * 4 + cq;
#pragma unroll
        for (int j = 0; j < 16; ++j) {
            const int col = j * 8 + g;
            uint2 w = sW[col * SPU + e];
            mma16816(accA[j], aA0, aA1, aA2, aA3, w.x, w.y);
            mma16816(accB[j], aB0, aB1, aB2, aB3, w.x, w.y);
        }
    }
}

// stage-2 GEMM + fused epilogue for one tile (acc consumed as A-fragments)
__device__ __forceinline__ void stage2_epi(float (&acc)[16][4],
                                           const uint2* __restrict__ W6,
                                           const uint2* __restrict__ W7,
                                           const float* __restrict__ c0p,
                                           const float* __restrict__ c1p,
                                           __half* __restrict__ sc_b,
                                           int t0, int t1, bool v0, bool v1,
                                           const float* __restrict__ sBf,
                                           float* __restrict__ sS, float* __restrict__ sQ,
                                           int w, int lane, int cq, int g) {
#pragma unroll
    for (int jb = 0; jb < 4; ++jb) {
        float a2[4][4];
#pragma unroll
        for (int jj = 0; jj < 4; ++jj) { a2[jj][0]=0.f; a2[jj][1]=0.f; a2[jj][2]=0.f; a2[jj][3]=0.f; }
#pragma unroll
        for (int c = 0; c < 8; ++c) {
            const uint2* sWc = (c < 4) ? W6 : W7;
            const uint32_t h0 = cvt2h(acc[2*c][0],   acc[2*c][1]);
            const uint32_t h1 = cvt2h(acc[2*c][2],   acc[2*c][3]);
            const uint32_t h2 = cvt2h(acc[2*c+1][0], acc[2*c+1][1]);
            const uint32_t h3 = cvt2h(acc[2*c+1][2], acc[2*c+1][3]);
            const int e = (c & 3) * 4 + cq;
#pragma unroll
            for (int jj = 0; jj < 4; ++jj) {
                const int col = (jb * 4 + jj) * 8 + g;
                uint2 ww = sWc[col * SPU + e];
                mma16816(a2[jj], h0, h1, h2, h3, ww.x, ww.y);
            }
        }
#pragma unroll
        for (int jj = 0; jj < 4; ++jj) {
            const int f = (jb * 4 + jj) * 8 + cq * 2;
            float2 cu0 = *reinterpret_cast<const float2*>(c0p + f);
            float2 cu1 = *reinterpret_cast<const float2*>(c1p + f);
            float add0 = cu0.x + a2[jj][0] + sBf[f];
            float add1 = cu0.y + a2[jj][1] + sBf[f + 1];
            float add2 = cu1.x + a2[jj][2] + sBf[f];
            float add3 = cu1.y + a2[jj][3] + sBf[f + 1];
            if (v0) { *reinterpret_cast<uint32_t*>(sc_b + (size_t)t0 * D_ + f) = cvt2h(add0, add1); }
            else { add0 = 0.f; add1 = 0.f; }
            if (v1) { *reinterpret_cast<uint32_t*>(sc_b + (size_t)t1 * D_ + f) = cvt2h(add2, add3); }
            else { add2 = 0.f; add3 = 0.f; }

            float s0 = add0 + add2, s1 = add1 + add3;
            float q0 = add0 * add0 + add2 * add2, q1 = add1 * add1 + add3 * add3;
#pragma unroll
            for (int o = 4; o < 32; o <<= 1) {
                s0 += __shfl_xor_sync(0xffffffffu, s0, o);
                s1 += __shfl_xor_sync(0xffffffffu, s1, o);
                q0 += __shfl_xor_sync(0xffffffffu, q0, o);
                q1 += __shfl_xor_sync(0xffffffffu, q1, o);
            }
            if (lane < 4) {
                sS[w * 128 + f] = s0; sS[w * 128 + f + 1] = s1;
                sQ[w * 128 + f] = q0; sQ[w * 128 + f + 1] = q1;
            }
        }
    }
}

__global__ void __launch_bounds__(256, 1)
main_kernel(const int* __restrict__ sn, const float* __restrict__ emb,
            const float* __restrict__ b_comb, const float* __restrict__ b_ff) {
    extern __shared__ char smem[];
    uint2* sbW = reinterpret_cast<uint2*>(smem);
    float* sBc = reinterpret_cast<float*>(smem + SMEM_W);
    float* sBf = sBc + 128;
    float* sS  = sBf + 128;                     // 2 slots x [8][128]
    float* sQ  = sS + 2048;

    const int tid  = threadIdx.x;
    const int w    = tid >> 5;
    const int lane = tid & 31;
    const int g    = lane >> 2;
    const int cq   = lane & 3;
    const int b    = blockIdx.y;

    const float* emb_b = emb + (size_t)b * NP1 * D_;
    const int*   sn_b  = sn  + (size_t)b * N_ * 2;
    __half*      sc_b  = g_added + (size_t)b * N_ * D_;

    // ---- stage ALL 8 weight sub-slices once (128KB) ----
#pragma unroll 4
    for (int i = tid; i < 8192; i += 256) {
        const int ss = i >> 10, idx = i & 1023;
        const int n = idx >> 3, ee = (idx & 7) * 2;
        cp16(sbW + ss * WBUF_UINT2 + n * SPU + ee, g_Wb + ss * 2048 + n * 16 + ee);
    }
    cp_commit();

    if (tid < 128) sBc[tid] = b_comb[tid];
    else           sBf[tid - 128] = b_ff[tid - 128];

    cp_wait<0>();
    __syncthreads();

    const uint2* W0 = sbW;
    const uint2* W1 = sbW + 1 * WBUF_UINT2;
    const uint2* W2 = sbW + 2 * WBUF_UINT2;
    const uint2* W3 = sbW + 3 * WBUF_UINT2;
    const uint2* W4 = sbW + 4 * WBUF_UINT2;
    const uint2* W5 = sbW + 5 * WBUF_UINT2;
    const uint2* W6 = sbW + 6 * WBUF_UINT2;
    const uint2* W7 = sbW + 7 * WBUF_UINT2;

    for (int tt = 0; tt < 2; ++tt) {
        const int tileA = blockIdx.x * 4 + tt * 2;
        const int tileB = tileA + 1;

        // tile A token rows
        const int tA0 = tileA * 128 + w * 16 + g;
        const int tA1 = tA0 + 8;
        const bool vA0 = (tA0 < N_), vA1 = (tA1 < N_);
        const int tA0c = vA0 ? tA0 : (N_ - 1);
        const int tA1c = vA1 ? tA1 : (N_ - 1);
        // tile B token rows
        const int tB0 = tileB * 128 + w * 16 + g;
        const int tB1 = tB0 + 8;
        const bool vB0 = (tB0 < N_), vB1 = (tB1 < N_);
        const int tB0c = vB0 ? tB0 : (N_ - 1);
        const int tB1c = vB1 ? tB1 : (N_ - 1);

        const int lA0 = sn_b[tA0c * 2],     lA1 = sn_b[tA1c * 2];
        const int rA0 = sn_b[tA0c * 2 + 1], rA1 = sn_b[tA1c * 2 + 1];
        const int lB0 = sn_b[tB0c * 2],     lB1 = sn_b[tB1c * 2];
        const int rB0 = sn_b[tB0c * 2 + 1], rB1 = sn_b[tB1c * 2 + 1];

        const float* cA0p = emb_b + (size_t)(1 + tA0c) * D_;
        const float* cA1p = emb_b + (size_t)(1 + tA1c) * D_;
        const float* cB0p = emb_b + (size_t)(1 + tB0c) * D_;
        const float* cB1p = emb_b + (size_t)(1 + tB1c) * D_;

        float accA[16][4], accB[16][4];
#pragma unroll
        for (int j = 0; j < 16; ++j) {
            accA[j][0]=0.f; accA[j][1]=0.f; accA[j][2]=0.f; accA[j][3]=0.f;
            accB[j][0]=0.f; accB[j][1]=0.f; accB[j][2]=0.f; accB[j][3]=0.f;
        }

        // ---- Stage 1: 6 K=64 sub-slices, each B-fragment shared by 2 tiles ----
        compute_slice_dual(W0, cA0p, cA1p, cB0p, cB1p, cq, g, accA, accB);
        compute_slice_dual(W1, cA0p + 64, cA1p + 64, cB0p + 64, cB1p + 64, cq, g, accA, accB);
        {
            const float* lA0p = emb_b + (size_t)lA0 * D_;
            const float* lA1p = emb_b + (size_t)lA1 * D_;
            const float* lB0p = emb_b + (size_t)lB0 * D_;
            const float* lB1p = emb_b + (size_t)lB1 * D_;
            compute_slice_dual(W2, lA0p, lA1p, lB0p, lB1p, cq, g, accA, accB);
            compute_slice_dual(W3, lA0p + 64, lA1p + 64, lB0p + 64, lB1p + 64, cq, g, accA, accB);
        }
        {
            const float* rA0p = emb_b + (size_t)rA0 * D_;
            const float* rA1p = emb_b + (size_t)rA1 * D_;
            const float* rB0p = emb_b + (size_t)rB0 * D_;
            const float* rB1p = emb_b + (size_t)rB1 * D_;
            compute_slice_dual(W4, rA0p, rA1p, rB0p, rB1p, cq, g, accA, accB);
            compute_slice_dual(W5, rA0p + 64, rA1p + 64, rB0p + 64, rB1p + 64, cq, g, accA, accB);
        }

        // bias + relu (both tiles)
#pragma unroll
        for (int j = 0; j < 16; ++j) {
            const int n0 = j * 8 + cq * 2;
            accA[j][0] = fmaxf(accA[j][0] + sBc[n0],     0.f);
            accA[j][1] = fmaxf(accA[j][1] + sBc[n0 + 1], 0.f);
            accA[j][2] = fmaxf(accA[j][2] + sBc[n0],     0.f);
            accA[j][3] = fmaxf(accA[j][3] + sBc[n0 + 1], 0.f);
            accB[j][0] = fmaxf(accB[j][0] + sBc[n0],     0.f);
            accB[j][1] = fmaxf(accB[j][1] + sBc[n0 + 1], 0.f);
            accB[j][2] = fmaxf(accB[j][2] + sBc[n0],     0.f);
            accB[j][3] = fmaxf(accB[j][3] + sBc[n0 + 1], 0.f);
        }

        // ---- Stage 2 + epilogue per tile (separate LN slots) ----
        stage2_epi(accA, W6, W7, cA0p, cA1p, sc_b, tA0, tA1, vA0, vA1,
                   sBf, sS, sQ, w, lane, cq, g);
        stage2_epi(accB, W6, W7, cB0p, cB1p, sc_b, tB0, tB1, vB0, vB1,
                   sBf, sS + 1024, sQ + 1024, w, lane, cq, g);

        __syncthreads();
        {
            const int slot = tid >> 7;               // 0 -> tileA, 1 -> tileB
            const int f = tid & 127;
            float S = 0.f, Q = 0.f;
#pragma unroll
            for (int ww = 0; ww < 8; ++ww) {
                S += sS[slot * 1024 + ww * 128 + f];
                Q += sQ[slot * 1024 + ww * 128 + f];
            }
            const size_t slot_g = ((size_t)b * TILES + tileA + slot) * D_ + f;
            g_partS[slot_g] = S;
            g_partQ[slot_g] = Q;
        }
        __syncthreads();
    }
}

// --------------------------- LN stats + normalize ----------------------------
__global__ void stats_kernel() {
    int b = blockIdx.x, f = threadIdx.x;
    float S = 0.f, Q = 0.f;
    for (int c = 0; c < TILES; ++c) {
        S += g_partS[((size_t)b * TILES + c) * D_ + f];
        Q += g_partQ[((size_t)b * TILES + c) * D_ + f];
    }
    float mean = S * (1.0f / N_);
    float var  = Q * (1.0f / N_) - mean * mean;
    g_mean[b * D_ + f] = mean;
    g_rstd[b * D_ + f] = rsqrtf(var + 1e-5f);
}

__global__ void __launch_bounds__(256)
norm_kernel(const float* __restrict__ norm_w, const float* __restrict__ norm_b,
            float* __restrict__ out) {
    int v = blockIdx.x * 256 + threadIdx.x;        // 4-elem index over 64*5000*32
    int b = v / (N_ * 32);
    int r = v - b * (N_ * 32);
    int t = r >> 5;
    int f4 = (r & 31) * 4;
    uint2 hh = *reinterpret_cast<const uint2*>(g_added + ((size_t)b * N_ + t) * D_ + f4);
    float2 x01 = __half22float2(*reinterpret_cast<__half2*>(&hh.x));
    float2 x23 = __half22float2(*reinterpret_cast<__half2*>(&hh.y));
    float4 m  = *reinterpret_cast<const float4*>(g_mean + b * D_ + f4);
    float4 s  = *reinterpret_cast<const float4*>(g_rstd + b * D_ + f4);
    float4 ww = *reinterpret_cast<const float4*>(norm_w + f4);
    float4 bb = *reinterpret_cast<const float4*>(norm_b + f4);
    float4 o;
    o.x = (x01.x - m.x) * s.x * ww.x + bb.x;
    o.y = (x01.y - m.y) * s.y * ww.y + bb.y;
    o.z = (x23.x - m.z) * s.z * ww.z + bb.z;
    o.w = (x23.y - m.w) * s.w * ww.w + bb.w;
    *reinterpret_cast<float4*>(out + ((size_t)b * NP1 + 1 + t) * D_ + f4) = o;
}

// ------------------------------- launcher ------------------------------------
extern "C" void kernel_launch(void* const* d_in, const int* in_sizes, int n_in,
                              void* d_out, int out_size) {
    int i0 = 0;
    for (int i = 0; i < n_in; ++i) if (in_sizes[i] == B_ * N_ * 2) { i0 = i; break; }
    const int*   sn      = (const int*)d_in[i0];
    const float* emb     = (const float*)d_in[i0 + 1];
    const float* w_left  = (const float*)d_in[i0 + 2];
    const float* w_right = (const float*)d_in[i0 + 3];
    const float* w_comb  = (const float*)d_in[i0 + 4];
    const float* b_comb  = (const float*)d_in[i0 + 5];
    const float* w_ff    = (const float*)d_in[i0 + 6];
    const float* b_ff    = (const float*)d_in[i0 + 7];
    const float* norm_w  = (const float*)d_in[i0 + 8];
    const float* norm_b  = (const float*)d_in[i0 + 9];
    float* out = (float*)d_out;

    cudaFuncSetAttribute(main_kernel, cudaFuncAttributeMaxDynamicSharedMemorySize, SMEM_BYTES);

    // depot row (token 0) passthrough
    cudaMemcpy2DAsync(out, (size_t)NP1 * D_ * sizeof(float),
                      emb, (size_t)NP1 * D_ * sizeof(float),
                      D_ * sizeof(float), B_, cudaMemcpyDeviceToDevice);

    prep_kernel<<<128, 128>>>(w_comb, w_left, w_right, w_ff);
    main_kernel<<<dim3(10, B_), 256, SMEM_BYTES>>>(sn, emb, b_comb, b_ff);
    stats_kernel<<<B_, 128>>>();
    norm_kernel<<<B_ * N_ * 32 / 256, 256>>>(norm_w, norm_b, out);
}

// round 12
// speedup vs baseline: 1.5451x; 1.5451x over previous
#include <cuda_runtime.h>
#include <cuda_fp16.h>
#include <cstdint>

#define B_   64
#define N_   5000
#define NP1  5001
#define D_   128
#define TILES 40
#define NWORK (B_ * TILES)     // 2560 (b, tile) work items
#define GRID_MAIN 148
#define SPU  20     // smem B row stride in uint2 (==4 mod 16 -> conflict-free LDS.64)

// ------------------------- device scratch (no allocs) -----------------------
__device__ uint2  g_Wb[8 * 128 * 16];                 // fused weights fp16, 8 K=64 sub-slices
__device__ __half g_added[(size_t)B_ * N_ * D_];      // fp16 'added' scratch (82MB)
__device__ float  g_partS[B_ * TILES * D_];
__device__ float  g_partQ[B_ * TILES * D_];
__device__ float  g_mean[B_ * D_];
__device__ float  g_rstd[B_ * D_];

// ------------------------------- helpers ------------------------------------
__device__ __forceinline__ uint32_t cvt2h(float x, float y) {
    __half2 h = __floats2half2_rn(x, y);
    return *reinterpret_cast<uint32_t*>(&h);
}

__device__ __forceinline__ void mma16816(float (&c)[4],
                                         uint32_t a0, uint32_t a1, uint32_t a2, uint32_t a3,
                                         uint32_t b0, uint32_t b1) {
    asm("mma.sync.aligned.m16n8k16.row.col.f32.f16.f16.f32 "
        "{%0,%1,%2,%3}, {%4,%5,%6,%7}, {%8,%9}, {%0,%1,%2,%3};"
        : "+f"(c[0]), "+f"(c[1]), "+f"(c[2]), "+f"(c[3])
        : "r"(a0), "r"(a1), "r"(a2), "r"(a3), "r"(b0), "r"(b1));
}

__device__ __forceinline__ void cp16(void* dst_smem, const void* src) {
    unsigned sa = (unsigned)__cvta_generic_to_shared(dst_smem);
    asm volatile("cp.async.cg.shared.global [%0], [%1], 16;\n" :: "r"(sa), "l"(src));
}
__device__ __forceinline__ void cp_commit() { asm volatile("cp.async.commit_group;\n"); }
template <int N>
__device__ __forceinline__ void cp_wait() { asm volatile("cp.async.wait_group %0;\n" :: "n"(N)); }

// -------------------------- fused weight prep --------------------------------
__global__ void prep_kernel(const float* __restrict__ w_comb,
                            const float* __restrict__ w_left,
                            const float* __restrict__ w_right,
                            const float* __restrict__ w_ff) {
    __shared__ float row[512];
    int n = blockIdx.x, k = threadIdx.x;          // 128 x 128
    row[k] = w_comb[n * 256 + k];
    float a1 = 0.f, a2 = 0.f;
    for (int m = 0; m < 128; ++m) {
        float wc = w_comb[n * 256 + 128 + m];
        a1 = fmaf(wc, w_left[m * 128 + k], a1);
        a2 = fmaf(wc, w_right[m * 128 + k], a2);
    }
    row[128 + k] = a1;
    row[256 + k] = a2;
    row[384 + k] = w_ff[n * 128 + k];
    __syncthreads();
    const int ss = k >> 4, e = k & 15;
    const int c = e >> 2, cq = e & 3;
    const int base = ss * 64;
    const int i0 = base + (c * 8 + cq) * 2;
    const int i1 = base + (c * 8 + cq + 4) * 2;
    uint2 w;
    w.x = cvt2h(row[i0], row[i0 + 1]);
    w.y = cvt2h(row[i1], row[i1 + 1]);
    g_Wb[(ss * 128 + n) * 16 + e] = w;
}

// --------------------------- main fused kernel -------------------------------
#define WBUF_UINT2 (128 * SPU)                           // 2560 uint2 = 20480 B
#define SMEM_W     (8 * WBUF_UINT2 * 8)                  // 163840
#define SMEM_BYTES (SMEM_W + 1024 + 8192)                // 173056

// one K=64 GEMM sub-slice over gathered rows p0/p1 (single fp16 term)
__device__ __forceinline__ void compute_slice(const uint2* __restrict__ sW,
                                              const float* __restrict__ p0,
                                              const float* __restrict__ p1,
                                              int cq, int g, float (&acc)[16][4]) {
#pragma unroll
    for (int c = 0; c < 4; ++c) {
        const int kc = c * 16 + cq * 2;
        float2 x0a = *reinterpret_cast<const float2*>(p0 + kc);
        float2 x0b = *reinterpret_cast<const float2*>(p0 + kc + 8);
        float2 x1a = *reinterpret_cast<const float2*>(p1 + kc);
        float2 x1b = *reinterpret_cast<const float2*>(p1 + kc + 8);
        const uint32_t a0 = cvt2h(x0a.x, x0a.y);
        const uint32_t a1 = cvt2h(x1a.x, x1a.y);
        const uint32_t a2 = cvt2h(x0b.x, x0b.y);
        const uint32_t a3 = cvt2h(x1b.x, x1b.y);
        const int e = c * 4 + cq;
#pragma unroll
        for (int j = 0; j < 16; ++j) {
            const int col = j * 8 + g;
            uint2 w = sW[col * SPU + e];
            mma16816(acc[j], a0, a1, a2, a3, w.x, w.y);
        }
    }
}

__global__ void __launch_bounds__(256, 1)
main_kernel(const int* __restrict__ sn, const float* __restrict__ emb,
            const float* __restrict__ b_comb, const float* __restrict__ b_ff) {
    extern __shared__ char smem[];
    uint2* sbW = reinterpret_cast<uint2*>(smem);                 // 8 resident slices
    float* sBc = reinterpret_cast<float*>(smem + SMEM_W);
    float* sBf = sBc + 128;
    float* sS  = sBf + 128;
    float* sQ  = sS + 8 * 128;

    const int tid  = threadIdx.x;
    const int w    = tid >> 5;
    const int lane = tid & 31;
    const int g    = lane >> 2;
    const int cq   = lane & 3;

    // ---- stage ALL 8 weight sub-slices once per CTA (128KB) ----
#pragma unroll 4
    for (int i = tid; i < 8192; i += 256) {
        const int ss = i >> 10, idx = i & 1023;
        const int n = idx >> 3, ee = (idx & 7) * 2;
        cp16(sbW + ss * WBUF_UINT2 + n * SPU + ee, g_Wb + ss * 2048 + n * 16 + ee);
    }
    cp_commit();

    if (tid < 128) sBc[tid] = b_comb[tid];
    else           sBf[tid - 128] = b_ff[tid - 128];

    cp_wait<0>();
    __syncthreads();                                   // weights + biases resident

    const uint2* W0 = sbW;
    const uint2* W1 = sbW + 1 * WBUF_UINT2;
    const uint2* W2 = sbW + 2 * WBUF_UINT2;
    const uint2* W3 = sbW + 3 * WBUF_UINT2;
    const uint2* W4 = sbW + 4 * WBUF_UINT2;
    const uint2* W5 = sbW + 5 * WBUF_UINT2;
    const uint2* W6 = sbW + 6 * WBUF_UINT2;
    const uint2* W7 = sbW + 7 * WBUF_UINT2;

    // ---- persistent loop over (b, tile) work items ----
    for (int it = blockIdx.x; it < NWORK; it += GRID_MAIN) {
        const int b    = it / TILES;
        const int tile = it - b * TILES;

        const float* emb_b = emb + (size_t)b * NP1 * D_;
        const int*   sn_b  = sn  + (size_t)b * N_ * 2;
        __half*      sc_b  = g_added + (size_t)b * N_ * D_;

        const int tokBase = tile * 128 + w * 16;
        const int t0 = tokBase + g;
        const int t1 = t0 + 8;
        const bool v0 = (t0 < N_), v1 = (t1 < N_);
        const int t0c = v0 ? t0 : (N_ - 1);
        const int t1c = v1 ? t1 : (N_ - 1);

        const int li0 = sn_b[t0c * 2],     li1 = sn_b[t1c * 2];
        const int ri0 = sn_b[t0c * 2 + 1], ri1 = sn_b[t1c * 2 + 1];
        const float* c0p = emb_b + (size_t)(1 + t0c) * D_;
        const float* c1p = emb_b + (size_t)(1 + t1c) * D_;
        const float* l0p = emb_b + (size_t)li0 * D_;
        const float* l1p = emb_b + (size_t)li1 * D_;
        const float* r0p = emb_b + (size_t)ri0 * D_;
        const float* r1p = emb_b + (size_t)ri1 * D_;

        float acc[16][4];
#pragma unroll
        for (int j = 0; j < 16; ++j) { acc[j][0]=0.f; acc[j][1]=0.f; acc[j][2]=0.f; acc[j][3]=0.f; }

        // ---- Stage 1: 6 K=64 sub-slices, weights resident, no barriers ----
        compute_slice(W0, c0p,      c1p,      cq, g, acc);
        compute_slice(W1, c0p + 64, c1p + 64, cq, g, acc);
        compute_slice(W2, l0p,      l1p,      cq, g, acc);
        compute_slice(W3, l0p + 64, l1p + 64, cq, g, acc);
        compute_slice(W4, r0p,      r1p,      cq, g, acc);
        compute_slice(W5, r0p + 64, r1p + 64, cq, g, acc);

        // bias + relu
#pragma unroll
        for (int j = 0; j < 16; ++j) {
            const int n0 = j * 8 + cq * 2;
            acc[j][0] = fmaxf(acc[j][0] + sBc[n0],     0.f);
            acc[j][1] = fmaxf(acc[j][1] + sBc[n0 + 1], 0.f);
            acc[j][2] = fmaxf(acc[j][2] + sBc[n0],     0.f);
            acc[j][3] = fmaxf(acc[j][3] + sBc[n0 + 1], 0.f);
        }

        // ---- Stage 2 + fused epilogue, j-blocks of 4 ----
#pragma unroll
        for (int jb = 0; jb < 4; ++jb) {
            float a2[4][4];
#pragma unroll
            for (int jj = 0; jj < 4; ++jj) { a2[jj][0]=0.f; a2[jj][1]=0.f; a2[jj][2]=0.f; a2[jj][3]=0.f; }
#pragma unroll
            for (int c = 0; c < 8; ++c) {
                const uint2* sWc = (c < 4) ? W6 : W7;
                const uint32_t h0 = cvt2h(acc[2*c][0],   acc[2*c][1]);
                const uint32_t h1 = cvt2h(acc[2*c][2],   acc[2*c][3]);
                const uint32_t h2 = cvt2h(acc[2*c+1][0], acc[2*c+1][1]);
                const uint32_t h3 = cvt2h(acc[2*c+1][2], acc[2*c+1][3]);
                const int e = (c & 3) * 4 + cq;
#pragma unroll
                for (int jj = 0; jj < 4; ++jj) {
                    const int col = (jb * 4 + jj) * 8 + g;
                    uint2 ww = sWc[col * SPU + e];
                    mma16816(a2[jj], h0, h1, h2, h3, ww.x, ww.y);
                }
            }
#pragma unroll
            for (int jj = 0; jj < 4; ++jj) {
                const int f = (jb * 4 + jj) * 8 + cq * 2;
                float2 cu0 = *reinterpret_cast<const float2*>(c0p + f);
                float2 cu1 = *reinterpret_cast<const float2*>(c1p + f);
                float add0 = cu0.x + a2[jj][0] + sBf[f];
                float add1 = cu0.y + a2[jj][1] + sBf[f + 1];
                float add2 = cu1.x + a2[jj][2] + sBf[f];
                float add3 = cu1.y + a2[jj][3] + sBf[f + 1];
                if (v0) { *reinterpret_cast<uint32_t*>(sc_b + (size_t)t0 * D_ + f) = cvt2h(add0, add1); }
                else { add0 = 0.f; add1 = 0.f; }
                if (v1) { *reinterpret_cast<uint32_t*>(sc_b + (size_t)t1 * D_ + f) = cvt2h(add2, add3); }
                else { add2 = 0.f; add3 = 0.f; }

                float s0 = add0 + add2, s1 = add1 + add3;
                float q0 = add0 * add0 + add2 * add2, q1 = add1 * add1 + add3 * add3;
#pragma unroll
                for (int o = 4; o < 32; o <<= 1) {
                    s0 += __shfl_xor_sync(0xffffffffu, s0, o);
                    s1 += __shfl_xor_sync(0xffffffffu, s1, o);
                    q0 += __shfl_xor_sync(0xffffffffu, q0, o);
                    q1 += __shfl_xor_sync(0xffffffffu, q1, o);
                }
                if (lane < 4) {
                    sS[w * 128 + f] = s0; sS[w * 128 + f + 1] = s1;
                    sQ[w * 128 + f] = q0; sQ[w * 128 + f + 1] = q1;
                }
            }
        }
        __syncthreads();
        if (tid < 128) {
            float S = 0.f, Q = 0.f;
#pragma unroll
            for (int ww = 0; ww < 8; ++ww) { S += sS[ww * 128 + tid]; Q += sQ[ww * 128 + tid]; }
            const size_t slot = ((size_t)b * TILES + tile) * D_ + tid;
            g_partS[slot] = S;
            g_partQ[slot] = Q;
        }
        __syncthreads();                                 // sS/sQ reuse next item
    }
}

// --------------------------- LN stats + normalize ----------------------------
__global__ void stats_kernel() {
    int b = blockIdx.x, f = threadIdx.x;
    float S = 0.f, Q = 0.f;
    for (int c = 0; c < TILES; ++c) {
        S += g_partS[((size_t)b * TILES + c) * D_ + f];
        Q += g_partQ[((size_t)b * TILES + c) * D_ + f];
    }
    float mean = S * (1.0f / N_);
    float var  = Q * (1.0f / N_) - mean * mean;
    g_mean[b * D_ + f] = mean;
    g_rstd[b * D_ + f] = rsqrtf(var + 1e-5f);
}

// each thread: 2 independent float4 groups (higher MLP)
__global__ void __launch_bounds__(256)
norm_kernel(const float* __restrict__ norm_w, const float* __restrict__ norm_b,
            float* __restrict__ out) {
    int v0 = blockIdx.x * 512 + threadIdx.x;       // 2 units, stride 256
#pragma unroll
    for (int u = 0; u < 2; ++u) {
        int v = v0 + u * 256;
        int b = v / (N_ * 32);
        int r = v - b * (N_ * 32);
        int t = r >> 5;
        int f4 = (r & 31) * 4;
        uint2 hh = *reinterpret_cast<const uint2*>(g_added + ((size_t)b * N_ + t) * D_ + f4);
        float2 x01 = __half22float2(*reinterpret_cast<__half2*>(&hh.x));
        float2 x23 = __half22float2(*reinterpret_cast<__half2*>(&hh.y));
        float4 m  = *reinterpret_cast<const float4*>(g_mean + b * D_ + f4);
        float4 s  = *reinterpret_cast<const float4*>(g_rstd + b * D_ + f4);
        float4 ww = *reinterpret_cast<const float4*>(norm_w + f4);
        float4 bb = *reinterpret_cast<const float4*>(norm_b + f4);
        float4 o;
        o.x = (x01.x - m.x) * s.x * ww.x + bb.x;
        o.y = (x01.y - m.y) * s.y * ww.y + bb.y;
        o.z = (x23.x - m.z) * s.z * ww.z + bb.z;
        o.w = (x23.y - m.w) * s.w * ww.w + bb.w;
        *reinterpret_cast<float4*>(out + ((size_t)b * NP1 + 1 + t) * D_ + f4) = o;
    }
}

// ------------------------------- launcher ------------------------------------
extern "C" void kernel_launch(void* const* d_in, const int* in_sizes, int n_in,
                              void* d_out, int out_size) {
    int i0 = 0;
    for (int i = 0; i < n_in; ++i) if (in_sizes[i] == B_ * N_ * 2) { i0 = i; break; }
    const int*   sn      = (const int*)d_in[i0];
    const float* emb     = (const float*)d_in[i0 + 1];
    const float* w_left  = (const float*)d_in[i0 + 2];
    const float* w_right = (const float*)d_in[i0 + 3];
    const float* w_comb  = (const float*)d_in[i0 + 4];
    const float* b_comb  = (const float*)d_in[i0 + 5];
    const float* w_ff    = (const float*)d_in[i0 + 6];
    const float* b_ff    = (const float*)d_in[i0 + 7];
    const float* norm_w  = (const float*)d_in[i0 + 8];
    const float* norm_b  = (const float*)d_in[i0 + 9];
    float* out = (float*)d_out;

    cudaFuncSetAttribute(main_kernel, cudaFuncAttributeMaxDynamicSharedMemorySize, SMEM_BYTES);

    // depot row (token 0) passthrough
    cudaMemcpy2DAsync(out, (size_t)NP1 * D_ * sizeof(float),
                      emb, (size_t)NP1 * D_ * sizeof(float),
                      D_ * sizeof(float), B_, cudaMemcpyDeviceToDevice);

    prep_kernel<<<128, 128>>>(w_comb, w_left, w_right, w_ff);
    main_kernel<<<GRID_MAIN, 256, SMEM_BYTES>>>(sn, emb, b_comb, b_ff);
    stats_kernel<<<B_, 128>>>();
    norm_kernel<<<B_ * N_ * 32 / 512, 256>>>(norm_w, norm_b, out);
}